// round 7
// baseline (speedup 1.0000x reference)
#include <cuda_runtime.h>
#include <cstdint>

// Decode-mode paged attention, fp32, GQA 4. Split-KV flash decode.
// Token-split warps: each warp owns 8 tokens of a 32-token tile, computes all 4 heads.
// q: [B,H,D] | k_pages,v_pages: [KVH,P,T,D] | lengths: [B] | page_indices: [B,PPS]

#define BB     32
#define HH     32
#define DD     128
#define KVHH   8
#define GG     4
#define NPAGE  2048
#define TT     64
#define PPSS   64
#define NSPLIT 16
#define PPER   (PPSS / NSPLIT)     // 4 pages per split
#define TOKSPL (PPER * TT)         // 256 tokens per split
#define TILE   32                  // tokens per smem tile (half page)
#define L2E    1.4426950408889634f
#define FULL   0xffffffffu

// Split-KV scratch (__device__ globals per allocation rules)
__device__ float g_m[NSPLIT * BB * HH];
__device__ float g_l[NSPLIT * BB * HH];
__device__ float g_o[NSPLIT * BB * HH * DD];

__device__ __forceinline__ void cp16(uint32_t dst, const void* src) {
    asm volatile("cp.async.cg.shared.global [%0], [%1], 16;\n" :: "r"(dst), "l"(src));
}
__device__ __forceinline__ float dot4(float4 a, float4 b) {
    return a.x * b.x + a.y * b.y + a.z * b.z + a.w * b.w;
}
__device__ __forceinline__ void fma4(float4& o, float p, float4 v) {
    o.x += p * v.x; o.y += p * v.y; o.z += p * v.z; o.w += p * v.w;
}
__device__ __forceinline__ void mul4(float4& o, float r) {
    o.x *= r; o.y *= r; o.z *= r; o.w *= r;
}

__global__ __launch_bounds__(128, 5)
void attn_partial(const float* __restrict__ q,
                  const float* __restrict__ kp,
                  const float* __restrict__ vp,
                  const int*   __restrict__ lengths,
                  const int*   __restrict__ pidx)
{
    __shared__ float4 ksm[2][TILE * 32];     // 32 KB, swizzled [t][c^t]
    __shared__ float4 qs4[GG][32];           // q[head][chunk]
    __shared__ float4 psm4[GG][8];           // p[warp][token] as (h0,h1,h2,h3)
    __shared__ float  msm[GG][GG], lsm[GG][GG];  // [warp][head]
    __shared__ float4 osm[GG][GG][32];       // [warp][head][lane]  8 KB

    const int split = blockIdx.x;
    const int kvh   = blockIdx.y;
    const int b     = blockIdx.z;
    const int tid   = threadIdx.x;
    const int warp  = tid >> 5;
    const int lane  = tid & 31;
    const int quad  = lane & 3;         // head (score phase) / chunk-group
    const int tloc  = lane >> 2;        // token within warp's 8 (score phase)
    const int myt   = (warp << 3) | tloc;   // token within tile 0..31

    const int len  = __ldg(&lengths[b]);
    const int tok0 = split * TOKSPL;
    const int ntok = min(len - tok0, TOKSPL);

    if (ntok <= 0) {
        const int slot = (split * BB + b) * HH + kvh * GG + warp;
        if (lane == 0) { g_m[slot] = -1e30f; g_l[slot] = 0.0f; }
        float4 z = make_float4(0.f, 0.f, 0.f, 0.f);
        *(float4*)&g_o[(size_t)slot * DD + 4 * lane] = z;
        return;
    }
    const int ntiles = (ntok + TILE - 1) / TILE;

    // q for the 4 heads of this kv group: warp h loads head h
    qs4[warp][lane] = *(const float4*)&q[((size_t)b * HH + kvh * GG + warp) * DD + 4 * lane];

    const uint32_t smem_base = (uint32_t)__cvta_generic_to_shared(&ksm[0][0]);
    const int pbase = b * PPSS + split * PPER;

    auto issue_copy = [&](int buf, int i) {
        const int page = __ldg(&pidx[pbase + (i >> 1)]);
        const float* base = kp + ((size_t)(kvh * NPAGE + page)) * TT * DD
                               + (size_t)(i & 1) * TILE * DD;
        #pragma unroll
        for (int j = 0; j < 8; ++j) {
            int idx = j * 128 + tid;
            int t = idx >> 5, c = idx & 31;
            uint32_t dst = smem_base
                         + (uint32_t)(buf * (TILE * 32) + t * 32 + (c ^ t)) * 16u;
            cp16(dst, base + t * DD + c * 4);
        }
        asm volatile("cp.async.commit_group;\n");
    };

    // per-lane state: m,l for head==quad over this warp's tokens;
    // o0..o3: heads 0..3, dims [4*lane, 4*lane+4)
    float  m = -1e30f, l = 0.0f;
    float4 o0 = make_float4(0,0,0,0), o1 = o0, o2 = o0, o3 = o0;

    issue_copy(0, 0);

    for (int i = 0; i < ntiles; ++i) {
        // ---- V prefetch for tile i (independent of smem pipeline) ----
        const int page_i = __ldg(&pidx[pbase + (i >> 1)]);
        const float* vb = vp + ((size_t)(kvh * NPAGE + page_i)) * TT * DD
                             + (size_t)(i & 1) * TILE * DD;
        float4 vpre[8];
        #pragma unroll
        for (int t = 0; t < 8; ++t)
            vpre[t] = __ldg((const float4*)&vb[(warp * 8 + t) * DD + 4 * lane]);

        if (i + 1 < ntiles) {
            issue_copy((i + 1) & 1, i + 1);
            asm volatile("cp.async.wait_group 1;\n");
        } else {
            asm volatile("cp.async.wait_group 0;\n");
        }
        __syncthreads();

        // ---- score: lane covers token myt, chunks c = quad*8+j, all 4 heads ----
        const float4* kb = &ksm[i & 1][0];
        float a0 = 0.f, a1 = 0.f, a2 = 0.f, a3 = 0.f;
        #pragma unroll
        for (int j = 0; j < 8; ++j) {
            const int c = (quad << 3) | j;
            const float4 k4 = kb[myt * 32 + (c ^ myt)];
            a0 += dot4(qs4[0][c], k4);
            a1 += dot4(qs4[1][c], k4);
            a2 += dot4(qs4[2][c], k4);
            a3 += dot4(qs4[3][c], k4);
        }
        // finish dots across the 4 chunk-groups (lanes of same token)
        a0 += __shfl_xor_sync(FULL, a0, 1); a0 += __shfl_xor_sync(FULL, a0, 2);
        a1 += __shfl_xor_sync(FULL, a1, 1); a1 += __shfl_xor_sync(FULL, a1, 2);
        a2 += __shfl_xor_sync(FULL, a2, 1); a2 += __shfl_xor_sync(FULL, a2, 2);
        a3 += __shfl_xor_sync(FULL, a3, 1); a3 += __shfl_xor_sync(FULL, a3, 2);
        float s = a0;
        if (quad == 1) s = a1;
        if (quad == 2) s = a2;
        if (quad == 3) s = a3;     // lane now holds score(head=quad, token=myt)
        if (tok0 + i * TILE + myt >= len) s = -1e30f;

        // ---- per-head softmax over this warp's 8 tokens (lanes w/ same quad) ----
        float pm = s;
        pm = fmaxf(pm, __shfl_xor_sync(FULL, pm, 4));
        pm = fmaxf(pm, __shfl_xor_sync(FULL, pm, 8));
        pm = fmaxf(pm, __shfl_xor_sync(FULL, pm, 16));

        const float newm = fmaxf(m, pm);
        const float r = exp2f((m - newm) * L2E);
        const float e = exp2f((s - newm) * L2E);
        float ls = e;
        ls += __shfl_xor_sync(FULL, ls, 4);
        ls += __shfl_xor_sync(FULL, ls, 8);
        ls += __shfl_xor_sync(FULL, ls, 16);
        l = l * r + ls;
        m = newm;

        // gather per-head rescale factors (lane base..base+3 are quads 0..3)
        const int base = lane & ~3;
        const float r0 = __shfl_sync(FULL, r, base);
        const float r1 = __shfl_sync(FULL, r, base + 1);
        const float r2 = __shfl_sync(FULL, r, base + 2);
        const float r3 = __shfl_sync(FULL, r, base + 3);
        mul4(o0, r0); mul4(o1, r1); mul4(o2, r2); mul4(o3, r3);

        // publish p: psm4[warp] laid out [token][head] = lane order
        ((float*)psm4[warp])[lane] = e;
        __syncwarp();

        // ---- o[h] += p * v : lane owns dims [4*lane..), loop warp's 8 tokens ----
        #pragma unroll
        for (int t = 0; t < 8; ++t) {
            const float4 pt = psm4[warp][t];
            const float4 v4 = vpre[t];
            fma4(o0, pt.x, v4);
            fma4(o1, pt.y, v4);
            fma4(o2, pt.z, v4);
            fma4(o3, pt.w, v4);
        }
        __syncthreads();   // buffer reuse guard
    }

    // ---- in-CTA combine across the 4 token-subset warps ----
    if (lane < 4) { msm[warp][lane] = m; lsm[warp][lane] = l; }
    __syncthreads();

    float fh0, fh1, fh2, fh3, Mout = 0.f, Lout = 0.f;
    {
        #pragma unroll
        for (int h = 0; h < 4; ++h) {
            const float M = fmaxf(fmaxf(msm[0][h], msm[1][h]),
                                  fmaxf(msm[2][h], msm[3][h]));
            float L = 0.f;
            #pragma unroll
            for (int w2 = 0; w2 < 4; ++w2)
                L += exp2f((msm[w2][h] - M) * L2E) * lsm[w2][h];
            const float f = exp2f((msm[warp][h] - M) * L2E);
            if (h == 0) fh0 = f;
            if (h == 1) fh1 = f;
            if (h == 2) fh2 = f;
            if (h == 3) fh3 = f;
            if (h == warp) { Mout = M; Lout = L; }
        }
    }
    mul4(o0, fh0); mul4(o1, fh1); mul4(o2, fh2); mul4(o3, fh3);
    osm[warp][0][lane] = o0;
    osm[warp][1][lane] = o1;
    osm[warp][2][lane] = o2;
    osm[warp][3][lane] = o3;
    __syncthreads();

    // warp w finalizes head h = w
    float4 acc = osm[0][warp][lane];
    float4 t1  = osm[1][warp][lane];
    float4 t2  = osm[2][warp][lane];
    float4 t3  = osm[3][warp][lane];
    acc.x += t1.x + t2.x + t3.x;
    acc.y += t1.y + t2.y + t3.y;
    acc.z += t1.z + t2.z + t3.z;
    acc.w += t1.w + t2.w + t3.w;

    const int slot = (split * BB + b) * HH + kvh * GG + warp;
    *(float4*)&g_o[(size_t)slot * DD + 4 * lane] = acc;
    if (lane == 0) { g_m[slot] = Mout; g_l[slot] = Lout; }
}

__global__ __launch_bounds__(128)
void attn_reduce(float* __restrict__ out)
{
    const int idx  = blockIdx.x * 4 + (threadIdx.x >> 5);  // (b*H + h)
    const int lane = threadIdx.x & 31;

    float M = -1e30f;
    #pragma unroll
    for (int j = 0; j < NSPLIT; ++j)
        M = fmaxf(M, g_m[j * BB * HH + idx]);

    float L = 0.0f;
    float4 acc = make_float4(0.f, 0.f, 0.f, 0.f);
    #pragma unroll
    for (int j = 0; j < NSPLIT; ++j) {
        const int sl = j * BB * HH + idx;
        const float f = exp2f((g_m[sl] - M) * L2E);
        L += f * g_l[sl];
        float4 ov = *(const float4*)&g_o[(size_t)sl * DD + 4 * lane];
        acc.x += f * ov.x;
        acc.y += f * ov.y;
        acc.z += f * ov.z;
        acc.w += f * ov.w;
    }

    const float inv = 1.0f / L;  // split 0 always non-empty -> L > 0
    float4 res = make_float4(acc.x * inv, acc.y * inv, acc.z * inv, acc.w * inv);
    *(float4*)&out[(size_t)idx * DD + 4 * lane] = res;
}

extern "C" void kernel_launch(void* const* d_in, const int* in_sizes, int n_in,
                              void* d_out, int out_size)
{
    const float* q   = (const float*)d_in[0];
    const float* kp  = (const float*)d_in[1];
    const float* vp  = (const float*)d_in[2];
    const int*   len = (const int*)d_in[3];
    const int*   pid = (const int*)d_in[4];
    float* out = (float*)d_out;

    dim3 grid(NSPLIT, KVHH, BB);
    attn_partial<<<grid, 128>>>(q, kp, vp, len, pid);
    attn_reduce<<<(BB * HH) / 4, 128>>>(out);
}

// round 10
// speedup vs baseline: 1.7752x; 1.7752x over previous
#include <cuda_runtime.h>
#include <cstdint>

// Decode-mode paged attention, fp32, GQA 4. Split-KV flash decode.
// R6 structure + triple-buffered cp.async K pipeline (distance 2) + V L1 prefetch.
// q: [B,H,D] | k_pages,v_pages: [KVH,P,T,D] | lengths: [B] | page_indices: [B,PPS]

#define BB     32
#define HH     32
#define DD     128
#define KVHH   8
#define GG     4
#define NPAGE  2048
#define TT     64
#define PPSS   64
#define NSPLIT 16
#define PPER   (PPSS / NSPLIT)     // 4 pages per split
#define TOKSPL (PPER * TT)         // 256 tokens per split
#define TILE   32                  // tokens per smem tile (half page)
#define NBUF   3
#define L2E    1.4426950408889634f

// Split-KV scratch (__device__ globals per allocation rules)
__device__ float g_m[NSPLIT * BB * HH];
__device__ float g_l[NSPLIT * BB * HH];
__device__ float g_o[NSPLIT * BB * HH * DD];

__device__ __forceinline__ void cp16(uint32_t dst, const void* src) {
    asm volatile("cp.async.cg.shared.global [%0], [%1], 16;\n" :: "r"(dst), "l"(src));
}

__global__ __launch_bounds__(128, 4)
void attn_partial(const float* __restrict__ q,
                  const float* __restrict__ kp,
                  const float* __restrict__ vp,
                  const int*   __restrict__ lengths,
                  const int*   __restrict__ pidx)
{
    // K tile triple buffer: [3][token 0..31][chunk 0..31] float4, XOR-swizzled
    __shared__ float4 ksm[NBUF][TILE * 32];   // 48 KB
    __shared__ float4 qs[GG][32];

    const int split = blockIdx.x;
    const int kvh   = blockIdx.y;
    const int b     = blockIdx.z;
    const int tid   = threadIdx.x;
    const int warp  = tid >> 5;      // GQA head within group
    const int lane  = tid & 31;
    const int h     = kvh * GG + warp;
    const int slot  = (split * BB + b) * HH + h;

    const int len  = __ldg(&lengths[b]);
    const int tok0 = split * TOKSPL;
    const int ntok = min(len - tok0, TOKSPL);

    if (ntok <= 0) {
        if (lane == 0) { g_m[slot] = -1e30f; g_l[slot] = 0.0f; }
        float4 z = make_float4(0.f, 0.f, 0.f, 0.f);
        *(float4*)&g_o[(size_t)slot * DD + 4 * lane] = z;
        return;
    }
    const int ntiles = (ntok + TILE - 1) / TILE;

    // q slice for this head: chunk c holds dims [4c,4c+4)
    qs[warp][lane] = *(const float4*)&q[((size_t)b * HH + h) * DD + 4 * lane];
    __syncwarp();

    const uint32_t smem_base = (uint32_t)__cvta_generic_to_shared(&ksm[0][0]);
    const int pbase = b * PPSS + split * PPER;

    // ---- async copy of K tile i into buffer buf (swizzled) ----
    auto issue_copy = [&](int buf, int i) {
        const int page = __ldg(&pidx[pbase + (i >> 1)]);
        const float* base = kp + ((size_t)(kvh * NPAGE + page)) * TT * DD
                               + (size_t)(i & 1) * TILE * DD;
        #pragma unroll
        for (int j = 0; j < 8; ++j) {
            int idx = j * 128 + tid;
            int t = idx >> 5, c = idx & 31;
            uint32_t dst = smem_base
                         + (uint32_t)(buf * (TILE * 32) + t * 32 + (c ^ t)) * 16u;
            cp16(dst, base + t * DD + c * 4);
        }
        asm volatile("cp.async.commit_group;\n");
    };

    float  m = -1e30f, l = 0.0f;
    float4 o = make_float4(0.f, 0.f, 0.f, 0.f);

    // Prologue: fill pipeline to depth 2
    issue_copy(0, 0);
    if (ntiles > 1) issue_copy(1, 1);

    for (int i = 0; i < ntiles; ++i) {
        const int page_i = __ldg(&pidx[pbase + (i >> 1)]);
        const float* vb = vp + ((size_t)(kvh * NPAGE + page_i)) * TT * DD
                             + (size_t)(i & 1) * TILE * DD;
        // V L1 warm-up: 128 threads cover the 128 x 128B lines of this V tile
        asm volatile("prefetch.global.L1 [%0];\n" :: "l"(vb + tid * 32));

        // Keep pipeline at distance 2
        if (i + 2 < ntiles) issue_copy((i + 2) % NBUF, i + 2);

        // Wait until buffer i is complete
        if (i + 3 <= ntiles)      asm volatile("cp.async.wait_group 2;\n");
        else if (i + 2 == ntiles) asm volatile("cp.async.wait_group 1;\n");
        else                      asm volatile("cp.async.wait_group 0;\n");
        __syncthreads();

        // ---- score: lane owns token = lane of this tile ----
        const float4* kb = &ksm[i % NBUF][0];
        float4 acc = make_float4(0.f, 0.f, 0.f, 0.f);
        #pragma unroll
        for (int c = 0; c < 32; ++c) {
            float4 q4 = qs[warp][c];                 // LDS broadcast
            float4 k4 = kb[lane * 32 + (c ^ lane)];  // conflict-free
            acc.x += q4.x * k4.x;
            acc.y += q4.y * k4.y;
            acc.z += q4.z * k4.z;
            acc.w += q4.w * k4.w;
        }
        float s = (acc.x + acc.y) + (acc.z + acc.w);
        if (tok0 + i * TILE + lane >= len) s = -1e30f;

        // ---- tile softmax (once per 32 tokens) ----
        float pm = s;
        pm = fmaxf(pm, __shfl_xor_sync(0xffffffffu, pm, 16));
        pm = fmaxf(pm, __shfl_xor_sync(0xffffffffu, pm, 8));
        pm = fmaxf(pm, __shfl_xor_sync(0xffffffffu, pm, 4));
        pm = fmaxf(pm, __shfl_xor_sync(0xffffffffu, pm, 2));
        pm = fmaxf(pm, __shfl_xor_sync(0xffffffffu, pm, 1));

        const float newm = fmaxf(m, pm);
        const float r = exp2f((m - newm) * L2E);
        o.x *= r; o.y *= r; o.z *= r; o.w *= r;
        l *= r;
        m = newm;

        const float e = exp2f((s - m) * L2E);   // 0 for masked tokens
        float ls = e;
        ls += __shfl_xor_sync(0xffffffffu, ls, 16);
        ls += __shfl_xor_sync(0xffffffffu, ls, 8);
        ls += __shfl_xor_sync(0xffffffffu, ls, 4);
        ls += __shfl_xor_sync(0xffffffffu, ls, 2);
        ls += __shfl_xor_sync(0xffffffffu, ls, 1);
        l += ls;

        // ---- o += p_t * v_t  (coalesced global V, L1-warmed) ----
        const float* vbl = vb + 4 * lane;
        #pragma unroll
        for (int t = 0; t < TILE; ++t) {
            const float pt = __shfl_sync(0xffffffffu, e, t);
            float4 v4 = *(const float4*)(vbl + t * DD);
            o.x += pt * v4.x;
            o.y += pt * v4.y;
            o.z += pt * v4.z;
            o.w += pt * v4.w;
        }
        __syncthreads();   // buffer reuse guard
    }

    if (lane == 0) { g_m[slot] = m; g_l[slot] = l; }
    *(float4*)&g_o[(size_t)slot * DD + 4 * lane] = o;
}

__global__ __launch_bounds__(128)
void attn_reduce(float* __restrict__ out)
{
    const int idx  = blockIdx.x * 4 + (threadIdx.x >> 5);  // (b*H + h)
    const int lane = threadIdx.x & 31;

    float M = -1e30f;
    #pragma unroll
    for (int j = 0; j < NSPLIT; ++j)
        M = fmaxf(M, g_m[j * BB * HH + idx]);

    float L = 0.0f;
    float4 acc = make_float4(0.f, 0.f, 0.f, 0.f);
    #pragma unroll
    for (int j = 0; j < NSPLIT; ++j) {
        const int sl = j * BB * HH + idx;
        const float f = exp2f((g_m[sl] - M) * L2E);
        L += f * g_l[sl];
        float4 ov = *(const float4*)&g_o[(size_t)sl * DD + 4 * lane];
        acc.x += f * ov.x;
        acc.y += f * ov.y;
        acc.z += f * ov.z;
        acc.w += f * ov.w;
    }

    const float inv = 1.0f / L;  // split 0 always non-empty -> L > 0
    float4 res = make_float4(acc.x * inv, acc.y * inv, acc.z * inv, acc.w * inv);
    *(float4*)&out[(size_t)idx * DD + 4 * lane] = res;
}

extern "C" void kernel_launch(void* const* d_in, const int* in_sizes, int n_in,
                              void* d_out, int out_size)
{
    const float* q   = (const float*)d_in[0];
    const float* kp  = (const float*)d_in[1];
    const float* vp  = (const float*)d_in[2];
    const int*   len = (const int*)d_in[3];
    const int*   pid = (const int*)d_in[4];
    float* out = (float*)d_out;

    dim3 grid(NSPLIT, KVHH, BB);
    attn_partial<<<grid, 128>>>(q, kp, vp, len, pid);
    attn_reduce<<<(BB * HH) / 4, 128>>>(out);
}

// round 14
// speedup vs baseline: 1.7863x; 1.0063x over previous
#include <cuda_runtime.h>
#include <cstdint>

// Decode-mode paged attention, fp32, GQA 4. Split-KV flash decode, fully fused.
// Triple-buffered cp.async K pipeline (distance 2) + V L1 prefetch +
// last-CTA-per-(b,kvh) in-kernel reduction (no second kernel).
// q: [B,H,D] | k_pages,v_pages: [KVH,P,T,D] | lengths: [B] | page_indices: [B,PPS]

#define BB     32
#define HH     32
#define DD     128
#define KVHH   8
#define GG     4
#define NPAGE  2048
#define TT     64
#define PPSS   64
#define NSPLIT 16
#define PPER   (PPSS / NSPLIT)     // 4 pages per split
#define TOKSPL (PPER * TT)         // 256 tokens per split
#define TILE   32                  // tokens per smem tile (half page)
#define NBUF   3
#define L2E    1.4426950408889634f

// Split-KV scratch + arrival counters (__device__ globals per allocation rules)
__device__ float g_m[NSPLIT * BB * HH];
__device__ float g_l[NSPLIT * BB * HH];
__device__ float g_o[NSPLIT * BB * HH * DD];
__device__ int   g_cnt[BB * KVHH];          // zero-init; last CTA resets -> replay-safe

__device__ __forceinline__ void cp16(uint32_t dst, const void* src) {
    asm volatile("cp.async.cg.shared.global [%0], [%1], 16;\n" :: "r"(dst), "l"(src));
}

__global__ __launch_bounds__(128, 4)
void attn_fused(const float* __restrict__ q,
                const float* __restrict__ kp,
                const float* __restrict__ vp,
                const int*   __restrict__ lengths,
                const int*   __restrict__ pidx,
                float*       __restrict__ out)
{
    // K tile triple buffer: [3][token 0..31][chunk 0..31] float4, XOR-swizzled
    __shared__ float4 ksm[NBUF][TILE * 32];   // 48 KB
    __shared__ float4 qs[GG][32];
    __shared__ int    s_last;

    const int split = blockIdx.x;
    const int kvh   = blockIdx.y;
    const int b     = blockIdx.z;
    const int tid   = threadIdx.x;
    const int warp  = tid >> 5;      // GQA head within group
    const int lane  = tid & 31;
    const int h     = kvh * GG + warp;
    const int slot  = (split * BB + b) * HH + h;

    const int len  = __ldg(&lengths[b]);
    const int tok0 = split * TOKSPL;
    const int ntok = min(len - tok0, TOKSPL);
    const int nact = min((len + TOKSPL - 1) / TOKSPL, NSPLIT);  // active splits >= 1

    if (ntok > 0) {
        const int ntiles = (ntok + TILE - 1) / TILE;

        // q slice for this head: chunk c holds dims [4c,4c+4)
        qs[warp][lane] = *(const float4*)&q[((size_t)b * HH + h) * DD + 4 * lane];

        const uint32_t smem_base = (uint32_t)__cvta_generic_to_shared(&ksm[0][0]);
        const int pbase = b * PPSS + split * PPER;

        auto issue_copy = [&](int buf, int i) {
            const int page = __ldg(&pidx[pbase + (i >> 1)]);
            const float* base = kp + ((size_t)(kvh * NPAGE + page)) * TT * DD
                                   + (size_t)(i & 1) * TILE * DD;
            #pragma unroll
            for (int j = 0; j < 8; ++j) {
                int idx = j * 128 + tid;
                int t = idx >> 5, c = idx & 31;
                uint32_t dst = smem_base
                             + (uint32_t)(buf * (TILE * 32) + t * 32 + (c ^ t)) * 16u;
                cp16(dst, base + t * DD + c * 4);
            }
            asm volatile("cp.async.commit_group;\n");
        };

        float  m = -1e30f, l = 0.0f;
        float4 o = make_float4(0.f, 0.f, 0.f, 0.f);

        // Prologue: fill pipeline to depth 2
        issue_copy(0, 0);
        if (ntiles > 1) issue_copy(1, 1);

        for (int i = 0; i < ntiles; ++i) {
            const int page_i = __ldg(&pidx[pbase + (i >> 1)]);
            const float* vb = vp + ((size_t)(kvh * NPAGE + page_i)) * TT * DD
                                 + (size_t)(i & 1) * TILE * DD;
            // V L1 warm-up: 128 threads cover the 128 x 128B lines of this V tile
            asm volatile("prefetch.global.L1 [%0];\n" :: "l"(vb + tid * 32));

            // Wait until buffer i is complete (newest in-flight group may remain)
            if (i + 1 < ntiles) asm volatile("cp.async.wait_group 1;\n");
            else                asm volatile("cp.async.wait_group 0;\n");
            __syncthreads();    // also proves all warps finished tile i-1

            // Safe now: (i+2)%3 == (i-1)%3, consumed last iteration
            if (i + 2 < ntiles) issue_copy((i + 2) % NBUF, i + 2);

            // ---- score: lane owns token = lane of this tile ----
            const float4* kb = &ksm[i % NBUF][0];
            float4 acc = make_float4(0.f, 0.f, 0.f, 0.f);
            #pragma unroll
            for (int c = 0; c < 32; ++c) {
                float4 q4 = qs[warp][c];                 // LDS broadcast
                float4 k4 = kb[lane * 32 + (c ^ lane)];  // conflict-free
                acc.x += q4.x * k4.x;
                acc.y += q4.y * k4.y;
                acc.z += q4.z * k4.z;
                acc.w += q4.w * k4.w;
            }
            float s = (acc.x + acc.y) + (acc.z + acc.w);
            if (tok0 + i * TILE + lane >= len) s = -1e30f;

            // ---- tile softmax ----
            float pm = s;
            pm = fmaxf(pm, __shfl_xor_sync(0xffffffffu, pm, 16));
            pm = fmaxf(pm, __shfl_xor_sync(0xffffffffu, pm, 8));
            pm = fmaxf(pm, __shfl_xor_sync(0xffffffffu, pm, 4));
            pm = fmaxf(pm, __shfl_xor_sync(0xffffffffu, pm, 2));
            pm = fmaxf(pm, __shfl_xor_sync(0xffffffffu, pm, 1));

            const float newm = fmaxf(m, pm);
            const float r = exp2f((m - newm) * L2E);
            o.x *= r; o.y *= r; o.z *= r; o.w *= r;
            l *= r;
            m = newm;

            const float e = exp2f((s - m) * L2E);   // 0 for masked tokens
            float ls = e;
            ls += __shfl_xor_sync(0xffffffffu, ls, 16);
            ls += __shfl_xor_sync(0xffffffffu, ls, 8);
            ls += __shfl_xor_sync(0xffffffffu, ls, 4);
            ls += __shfl_xor_sync(0xffffffffu, ls, 2);
            ls += __shfl_xor_sync(0xffffffffu, ls, 1);
            l += ls;

            // ---- o += p_t * v_t  (coalesced global V, L1-warmed) ----
            const float* vbl = vb + 4 * lane;
            #pragma unroll
            for (int t = 0; t < TILE; ++t) {
                const float pt = __shfl_sync(0xffffffffu, e, t);
                float4 v4 = *(const float4*)(vbl + t * DD);
                o.x += pt * v4.x;
                o.y += pt * v4.y;
                o.z += pt * v4.z;
                o.w += pt * v4.w;
            }
        }

        if (lane == 0) { g_m[slot] = m; g_l[slot] = l; }
        *(float4*)&g_o[(size_t)slot * DD + 4 * lane] = o;
        __threadfence();
        __syncthreads();
    }

    // ---- arrival count; last CTA of (b,kvh) reduces its 4 heads ----
    if (tid == 0)
        s_last = (atomicAdd(&g_cnt[b * KVHH + kvh], 1) == NSPLIT - 1);
    __syncthreads();

    if (s_last) {
        __threadfence();   // acquire: see all split CTAs' g_* writes
        const int idx = b * HH + kvh * GG + warp;   // this warp's (b,h)

        float M = -1e30f;
        for (int j = 0; j < nact; ++j)
            M = fmaxf(M, g_m[j * BB * HH + idx]);

        float L = 0.0f;
        float4 acc = make_float4(0.f, 0.f, 0.f, 0.f);
        for (int j = 0; j < nact; ++j) {
            const int sl = j * BB * HH + idx;
            const float f = exp2f((g_m[sl] - M) * L2E);
            L += f * g_l[sl];
            float4 ov = *(const float4*)&g_o[(size_t)sl * DD + 4 * lane];
            acc.x += f * ov.x;
            acc.y += f * ov.y;
            acc.z += f * ov.z;
            acc.w += f * ov.w;
        }

        const float inv = 1.0f / L;   // split 0 always non-empty -> L > 0
        float4 res = make_float4(acc.x * inv, acc.y * inv, acc.z * inv, acc.w * inv);
        *(float4*)&out[(size_t)idx * DD + 4 * lane] = res;

        if (tid == 0) g_cnt[b * KVHH + kvh] = 0;   // reset for graph replay
    }
}

extern "C" void kernel_launch(void* const* d_in, const int* in_sizes, int n_in,
                              void* d_out, int out_size)
{
    const float* q   = (const float*)d_in[0];
    const float* kp  = (const float*)d_in[1];
    const float* vp  = (const float*)d_in[2];
    const int*   len = (const int*)d_in[3];
    const int*   pid = (const int*)d_in[4];
    float* out = (float*)d_out;

    dim3 grid(NSPLIT, KVHH, BB);
    attn_fused<<<grid, 128>>>(q, kp, vp, len, pid, out);
}